// round 16
// baseline (speedup 1.0000x reference)
#include <cuda_runtime.h>
#include <cuda_bf16.h>
#include <cuda_fp16.h>
#include <stdint.h>

#define DEV __device__ __forceinline__

static constexpr int Bn  = 8192;
static constexpr int DIN = 1024;
static constexpr int Dd  = 768;
static constexpr int Cc  = 16384;

// ---- scratch: device globals (no allocation allowed) ----
__device__ __align__(1024) __half g_Xh[(size_t)Bn * DIN];
__device__ __align__(1024) __half g_Wh[(size_t)Dd * DIN];          // W^T
__device__ __align__(1024) __half g_E [(size_t)Bn * Dd];           // fp16 embedding
__device__ __align__(1024) __half g_Ch[(size_t)Cc * Dd];           // fp16 centroids
__device__ float g_esqp[(size_t)Bn * 12];   // per-(ntile,warp_n) partials
__device__ float g_esq[Bn];
__device__ float g_csq[Cc];

// ---------------- PTX helpers ----------------
DEV uint32_t smem_u32(const void* p){
    uint32_t a;
    asm("{ .reg .u64 t; cvta.to.shared.u64 t, %1; cvt.u32.u64 %0, t; }" : "=r"(a) : "l"(p));
    return a;
}
DEV uint32_t swz(uint32_t off){ return off ^ ((off >> 3) & 0x70); }   // SW128
DEV void cp16(uint32_t dst, const void* src){
    asm volatile("cp.async.cg.shared.global [%0], [%1], 16;" :: "r"(dst), "l"(src) : "memory");
}
DEV void cp_commit(){ asm volatile("cp.async.commit_group;" ::: "memory"); }
template<int N> DEV void cp_wait(){ asm volatile("cp.async.wait_group %0;" :: "n"(N) : "memory"); }

DEV void ldsm4(uint32_t* r, uint32_t addr){
    asm volatile("ldmatrix.sync.aligned.m8n8.x4.shared.b16 {%0,%1,%2,%3}, [%4];"
                 : "=r"(r[0]), "=r"(r[1]), "=r"(r[2]), "=r"(r[3]) : "r"(addr));
}
DEV void mma_f16(uint32_t* c, const uint32_t* a, uint32_t b0, uint32_t b1){
    asm volatile(
        "mma.sync.aligned.m16n8k16.row.col.f16.f16.f16.f16 "
        "{%0,%1}, {%2,%3,%4,%5}, {%6,%7}, {%0,%1};"
        : "+r"(c[0]), "+r"(c[1])
        : "r"(a[0]), "r"(a[1]), "r"(a[2]), "r"(a[3]), "r"(b0), "r"(b1));
}

// ---------------- prep kernels ----------------
__global__ void prep_x(const float4* __restrict__ x){
    size_t i = (size_t)blockIdx.x * blockDim.x + threadIdx.x;
    float4 v = x[i];
    reinterpret_cast<__half2*>(g_Xh)[2*i]   = __floats2half2_rn(v.x, v.y);
    reinterpret_cast<__half2*>(g_Xh)[2*i+1] = __floats2half2_rn(v.z, v.w);
}

__global__ void prep_w(const float* __restrict__ W){
    __shared__ float t[32][33];
    const int bx = blockIdx.x, by = blockIdx.y;
    const int tx = threadIdx.x, ty = threadIdx.y;    // (32,8)
    #pragma unroll
    for (int i = 0; i < 32; i += 8)
        t[ty + i][tx] = W[(size_t)(by*32 + ty + i)*Dd + bx*32 + tx];
    __syncthreads();
    #pragma unroll
    for (int i = 0; i < 32; i += 8)
        g_Wh[(size_t)(bx*32 + ty + i)*DIN + by*32 + tx] = __float2half_rn(t[tx][ty + i]);
}

__global__ void prep_cent(const float* __restrict__ cent){
    const int row = blockIdx.x, tid = threadIdx.x;   // 256 threads
    const float4* src4 = reinterpret_cast<const float4*>(cent + (size_t)row * Dd);
    __half2* dst2 = reinterpret_cast<__half2*>(g_Ch + (size_t)row * Dd);
    float s = 0.f;
    if (tid < 192){
        float4 v = src4[tid];
        s = v.x*v.x + v.y*v.y + v.z*v.z + v.w*v.w;
        dst2[tid*2]   = __floats2half2_rn(v.x, v.y);
        dst2[tid*2+1] = __floats2half2_rn(v.z, v.w);
    }
    __shared__ float red[8];
    #pragma unroll
    for (int o = 16; o; o >>= 1) s += __shfl_down_sync(0xffffffffu, s, o);
    if ((tid & 31) == 0) red[tid >> 5] = s;
    __syncthreads();
    if (tid < 8){
        s = red[tid];
        #pragma unroll
        for (int o = 4; o; o >>= 1) s += __shfl_down_sync(0xffu, s, o);
        if (tid == 0) g_csq[row] = s;
    }
}

__global__ void combine_esq(){
    const int row = blockIdx.x * blockDim.x + threadIdx.x;
    const float* p = g_esqp + (size_t)row * 12;
    float s = 0.f;
    #pragma unroll
    for (int k = 0; k < 12; k++) s += p[k];
    g_esq[row] = s;
}

// ======== gemm_e: CTA 128x128, 4 warps (2x2 of 64x64), BK=64, 2 stages, 3 CTA/SM ========
static constexpr int A_ST1  = 128 * 128;             // 16 KB
static constexpr int STAGE1 = 2 * A_ST1;             // 32 KB
static constexpr int SMEM1  = 2 * STAGE1;            // 64 KB

__global__ void __launch_bounds__(128, 3)
gemm_e(const __half* __restrict__ A, const __half* __restrict__ B)
{
    constexpr int NT = DIN / 64;                     // 16 k-chunks
    constexpr int LD = DIN * 2;

    extern __shared__ char smem[];
    const uint32_t sb = smem_u32(smem);
    const int tid = threadIdx.x, wid = tid >> 5, lane = tid & 31;
    const int warp_m = wid >> 1, warp_n = wid & 1;   // 2 x 2
    const int m0 = blockIdx.x * 128, n0 = blockIdx.y * 128;

    const int ldrow = tid >> 3, ldc = (tid & 7) * 16;
    const char* gAr = reinterpret_cast<const char*>(A) + (size_t)(m0 + ldrow) * LD + ldc;
    const char* gBr = reinterpret_cast<const char*>(B) + (size_t)(n0 + ldrow) * LD + ldc;
    const uint32_t sOff0 = swz((uint32_t)(ldrow*128 + ldc));

    auto load_stage = [&](int kc){
        const uint32_t base = sb + (kc & 1) * STAGE1 + sOff0;
        const size_t koff = (size_t)kc * 128;
        #pragma unroll
        for (int i = 0; i < 8; i++)
            cp16(base + i*2048, gAr + (size_t)(i*16)*LD + koff);
        #pragma unroll
        for (int i = 0; i < 8; i++)
            cp16(base + A_ST1 + i*2048, gBr + (size_t)(i*16)*LD + koff);
        cp_commit();
    };

    uint32_t hacc[4][8][2];
    #pragma unroll
    for (int i = 0; i < 4; i++)
        #pragma unroll
        for (int j = 0; j < 8; j++){ hacc[i][j][0] = 0u; hacc[i][j][1] = 0u; }

    load_stage(0); load_stage(1);
    const int lrow = lane & 15, lcol = (lane >> 4) * 16;
    const uint32_t aoff0 = swz((uint32_t)((warp_m*64 + lrow)*128 + lcol));
    const uint32_t boff0 = A_ST1 + swz((uint32_t)((warp_n*64 + lrow)*128 + lcol));

    for (int kc = 0; kc < NT; kc++){
        cp_wait<1>();
        __syncthreads();
        const uint32_t sbs = sb + (kc & 1) * STAGE1;
        #pragma unroll
        for (int ks = 0; ks < 4; ks++){
            uint32_t a[4][4], b[4][4];
            const uint32_t kx = (uint32_t)(ks*32);
            const uint32_t axk = sbs + (aoff0 ^ kx);
            const uint32_t bxk = sbs + (boff0 ^ kx);
            #pragma unroll
            for (int i = 0; i < 4; i++) ldsm4(a[i], axk + i*2048);
            #pragma unroll
            for (int j = 0; j < 4; j++) ldsm4(b[j], bxk + j*2048);
            #pragma unroll
            for (int i = 0; i < 4; i++)
                #pragma unroll
                for (int j2 = 0; j2 < 8; j2++)
                    mma_f16(hacc[i][j2], a[i], b[j2>>1][j2&1], b[j2>>1][2 + (j2&1)]);
        }
        __syncthreads();
        if (kc + 2 < NT) load_stage(kc + 2);
        else             cp_commit();                 // uniform group counting
    }

    const int quad = lane >> 2, tq = lane & 3;
    const int slot = blockIdx.y * 2 + warp_n;
    #pragma unroll
    for (int i = 0; i < 4; i++){
        const int mr0 = m0 + warp_m*64 + i*16 + quad;
        float s0 = 0.f, s1 = 0.f;
        #pragma unroll
        for (int j2 = 0; j2 < 8; j2++){
            const int n = n0 + warp_n*64 + j2*8 + tq*2;
            __half2 h0 = *reinterpret_cast<__half2*>(&hacc[i][j2][0]);
            __half2 h1 = *reinterpret_cast<__half2*>(&hacc[i][j2][1]);
            *reinterpret_cast<__half2*>(g_E + (size_t)mr0 * Dd + n)     = h0;
            *reinterpret_cast<__half2*>(g_E + (size_t)(mr0+8) * Dd + n) = h1;
            float2 f0 = __half22float2(h0), f1 = __half22float2(h1);
            s0 += f0.x*f0.x + f0.y*f0.y;
            s1 += f1.x*f1.x + f1.y*f1.y;
        }
        #pragma unroll
        for (int o = 1; o < 4; o <<= 1){
            s0 += __shfl_xor_sync(0xffffffffu, s0, o);
            s1 += __shfl_xor_sync(0xffffffffu, s1, o);
        }
        if (tq == 0){
            g_esqp[(size_t)mr0     * 12 + slot] = s0;
            g_esqp[(size_t)(mr0+8) * 12 + slot] = s1;
        }
    }
}

// ======== gemm_h: CTA 128x128, 8 warps (4x2 of 32x64), BK=64, 2 stages, 3 CTA/SM ========
// 24 warps/SM (6/SMSP) for latency hiding; 85-reg budget enforced.
static constexpr int A_ST2  = 128 * 128;             // 16 KB
static constexpr int STAGE2 = 2 * A_ST2;             // 32 KB
static constexpr int SMEM2  = 2 * STAGE2;            // 64 KB

__global__ void __launch_bounds__(256, 3)
gemm_h(const __half* __restrict__ A, const __half* __restrict__ B, float* __restrict__ out)
{
    constexpr int NT = Dd / 64;                      // 12 k-chunks
    constexpr int LD = Dd * 2;

    extern __shared__ char smem[];
    const uint32_t sb = smem_u32(smem);
    const int tid = threadIdx.x, wid = tid >> 5, lane = tid & 31;
    const int warp_m = wid >> 1, warp_n = wid & 1;   // 4 x 2, warp tile 32x64
    const int m0 = blockIdx.x * 128, n0 = blockIdx.y * 128;

    const int ldrow = tid >> 3, ldc = (tid & 7) * 16;   // ldrow 0..31
    const char* gAr = reinterpret_cast<const char*>(A) + (size_t)(m0 + ldrow) * LD + ldc;
    const char* gBr = reinterpret_cast<const char*>(B) + (size_t)(n0 + ldrow) * LD + ldc;
    const uint32_t sOff0 = swz((uint32_t)(ldrow*128 + ldc));   // rows step 32 -> +4096 folds

    auto load_stage = [&](int kc){
        const uint32_t base = sb + (kc & 1) * STAGE2 + sOff0;
        const size_t koff = (size_t)kc * 128;
        #pragma unroll
        for (int i = 0; i < 4; i++)                  // A: 128 rows
            cp16(base + i*4096, gAr + (size_t)(i*32)*LD + koff);
        #pragma unroll
        for (int i = 0; i < 4; i++)                  // B: 128 rows
            cp16(base + A_ST2 + i*4096, gBr + (size_t)(i*32)*LD + koff);
        cp_commit();
    };

    uint32_t hacc[2][8][2];
    #pragma unroll
    for (int i = 0; i < 2; i++)
        #pragma unroll
        for (int j = 0; j < 8; j++){ hacc[i][j][0] = 0u; hacc[i][j][1] = 0u; }

    load_stage(0); load_stage(1);
    const int lrow = lane & 15, lcol = (lane >> 4) * 16;
    const uint32_t aoff0 = swz((uint32_t)((warp_m*32 + lrow)*128 + lcol));
    const uint32_t boff0 = A_ST2 + swz((uint32_t)((warp_n*64 + lrow)*128 + lcol));

    for (int kc = 0; kc < NT; kc++){
        cp_wait<1>();
        __syncthreads();
        const uint32_t sbs = sb + (kc & 1) * STAGE2;
        #pragma unroll
        for (int ks = 0; ks < 4; ks++){
            uint32_t a[2][4], b[4][4];
            const uint32_t kx = (uint32_t)(ks*32);
            const uint32_t axk = sbs + (aoff0 ^ kx);
            const uint32_t bxk = sbs + (boff0 ^ kx);
            #pragma unroll
            for (int i = 0; i < 2; i++) ldsm4(a[i], axk + i*2048);
            #pragma unroll
            for (int j = 0; j < 4; j++) ldsm4(b[j], bxk + j*2048);
            #pragma unroll
            for (int i = 0; i < 2; i++)
                #pragma unroll
                for (int j2 = 0; j2 < 8; j2++)
                    mma_f16(hacc[i][j2], a[i], b[j2>>1][j2&1], b[j2>>1][2 + (j2&1)]);
        }
        __syncthreads();
        if (kc + 2 < NT) load_stage(kc + 2);
        else             cp_commit();
    }

    const int quad = lane >> 2, tq = lane & 3;
    #pragma unroll
    for (int i = 0; i < 2; i++){
        const int mr0 = m0 + warp_m*32 + i*16 + quad;
        const float e0 = __ldg(&g_esq[mr0]), e1 = __ldg(&g_esq[mr0 + 8]);
        #pragma unroll
        for (int j2 = 0; j2 < 8; j2++){
            const int n = n0 + warp_n*64 + j2*8 + tq*2;
            const float cs0 = __ldg(&g_csq[n]), cs1 = __ldg(&g_csq[n+1]);
            float2 lo = __half22float2(*reinterpret_cast<__half2*>(&hacc[i][j2][0]));
            float2 hi = __half22float2(*reinterpret_cast<__half2*>(&hacc[i][j2][1]));
            float2 v0 = make_float2(2.f*lo.x - e0 - cs0, 2.f*lo.y - e0 - cs1);
            float2 v1 = make_float2(2.f*hi.x - e1 - cs0, 2.f*hi.y - e1 - cs1);
            *reinterpret_cast<float2*>(out + (size_t)mr0 * Cc + n)     = v0;
            *reinterpret_cast<float2*>(out + (size_t)(mr0+8) * Cc + n) = v1;
        }
    }
}

extern "C" void kernel_launch(void* const* d_in, const int* in_sizes, int n_in,
                              void* d_out, int out_size)
{
    const float* x = (const float*)d_in[0];
    const float* W = (const float*)d_in[1];
    const float* c = (const float*)d_in[2];
    float* out = (float*)d_out;

    cudaFuncSetAttribute(gemm_e, cudaFuncAttributeMaxDynamicSharedMemorySize, SMEM1);
    cudaFuncSetAttribute(gemm_h, cudaFuncAttributeMaxDynamicSharedMemorySize, SMEM2);

    prep_x<<<(Bn * DIN / 4) / 256, 256>>>(reinterpret_cast<const float4*>(x));
    prep_w<<<dim3(Dd / 32, DIN / 32), dim3(32, 8)>>>(W);
    prep_cent<<<Cc, 256>>>(c);

    __half *xh, *wh, *eh, *ch;
    cudaGetSymbolAddress((void**)&xh, g_Xh);
    cudaGetSymbolAddress((void**)&wh, g_Wh);
    cudaGetSymbolAddress((void**)&eh, g_E);
    cudaGetSymbolAddress((void**)&ch, g_Ch);

    gemm_e<<<dim3(Bn / 128, Dd / 128), 128, SMEM1>>>(xh, wh);
    combine_esq<<<Bn / 256, 256>>>();
    gemm_h<<<dim3(Bn / 128, Cc / 128), 256, SMEM2>>>(eh, ch, out);
}

// round 17
// speedup vs baseline: 1.0499x; 1.0499x over previous
#include <cuda_runtime.h>
#include <cuda_bf16.h>
#include <cuda_fp16.h>
#include <stdint.h>

#define DEV __device__ __forceinline__

static constexpr int Bn  = 8192;
static constexpr int DIN = 1024;
static constexpr int Dd  = 768;
static constexpr int Cc  = 16384;

// ---- scratch: device globals (no allocation allowed) ----
__device__ __align__(1024) __half g_Xh[(size_t)Bn * DIN];
__device__ __align__(1024) __half g_Wh[(size_t)Dd * DIN];          // W^T
__device__ __align__(1024) __half g_E [(size_t)Bn * Dd];           // fp16 embedding
__device__ __align__(1024) __half g_Ch[(size_t)Cc * Dd];           // fp16 centroids
__device__ float g_esqp[(size_t)Bn * 12];   // per-(ntile,warp_n) partials
__device__ float g_esq[Bn];
__device__ float g_csq[Cc];

// ---------------- PTX helpers ----------------
DEV uint32_t smem_u32(const void* p){
    uint32_t a;
    asm("{ .reg .u64 t; cvta.to.shared.u64 t, %1; cvt.u32.u64 %0, t; }" : "=r"(a) : "l"(p));
    return a;
}
DEV uint32_t swz(uint32_t off){ return off ^ ((off >> 3) & 0x70); }   // SW128
DEV void cp16(uint32_t dst, const void* src){
    asm volatile("cp.async.cg.shared.global [%0], [%1], 16;" :: "r"(dst), "l"(src) : "memory");
}
DEV void cp_commit(){ asm volatile("cp.async.commit_group;" ::: "memory"); }
template<int N> DEV void cp_wait(){ asm volatile("cp.async.wait_group %0;" :: "n"(N) : "memory"); }

DEV void ldsm4(uint32_t* r, uint32_t addr){
    asm volatile("ldmatrix.sync.aligned.m8n8.x4.shared.b16 {%0,%1,%2,%3}, [%4];"
                 : "=r"(r[0]), "=r"(r[1]), "=r"(r[2]), "=r"(r[3]) : "r"(addr));
}
DEV void mma_f16(uint32_t* c, const uint32_t* a, uint32_t b0, uint32_t b1){
    asm volatile(
        "mma.sync.aligned.m16n8k16.row.col.f16.f16.f16.f16 "
        "{%0,%1}, {%2,%3,%4,%5}, {%6,%7}, {%0,%1};"
        : "+r"(c[0]), "+r"(c[1])
        : "r"(a[0]), "r"(a[1]), "r"(a[2]), "r"(a[3]), "r"(b0), "r"(b1));
}

// ---------------- prep kernels ----------------
__global__ void prep_x(const float4* __restrict__ x){
    size_t i = (size_t)blockIdx.x * blockDim.x + threadIdx.x;
    float4 v = x[i];
    reinterpret_cast<__half2*>(g_Xh)[2*i]   = __floats2half2_rn(v.x, v.y);
    reinterpret_cast<__half2*>(g_Xh)[2*i+1] = __floats2half2_rn(v.z, v.w);
}

__global__ void prep_w(const float* __restrict__ W){
    __shared__ float t[32][33];
    const int bx = blockIdx.x, by = blockIdx.y;
    const int tx = threadIdx.x, ty = threadIdx.y;    // (32,8)
    #pragma unroll
    for (int i = 0; i < 32; i += 8)
        t[ty + i][tx] = W[(size_t)(by*32 + ty + i)*Dd + bx*32 + tx];
    __syncthreads();
    #pragma unroll
    for (int i = 0; i < 32; i += 8)
        g_Wh[(size_t)(bx*32 + ty + i)*DIN + by*32 + tx] = __float2half_rn(t[tx][ty + i]);
}

__global__ void prep_cent(const float* __restrict__ cent){
    const int row = blockIdx.x, tid = threadIdx.x;   // 256 threads
    const float4* src4 = reinterpret_cast<const float4*>(cent + (size_t)row * Dd);
    __half2* dst2 = reinterpret_cast<__half2*>(g_Ch + (size_t)row * Dd);
    float s = 0.f;
    if (tid < 192){
        float4 v = src4[tid];
        s = v.x*v.x + v.y*v.y + v.z*v.z + v.w*v.w;
        dst2[tid*2]   = __floats2half2_rn(v.x, v.y);
        dst2[tid*2+1] = __floats2half2_rn(v.z, v.w);
    }
    __shared__ float red[8];
    #pragma unroll
    for (int o = 16; o; o >>= 1) s += __shfl_down_sync(0xffffffffu, s, o);
    if ((tid & 31) == 0) red[tid >> 5] = s;
    __syncthreads();
    if (tid < 8){
        s = red[tid];
        #pragma unroll
        for (int o = 4; o; o >>= 1) s += __shfl_down_sync(0xffu, s, o);
        if (tid == 0) g_csq[row] = s;
    }
}

__global__ void combine_esq(){
    const int row = blockIdx.x * blockDim.x + threadIdx.x;
    const float* p = g_esqp + (size_t)row * 12;
    float s = 0.f;
    #pragma unroll
    for (int k = 0; k < 12; k++) s += p[k];
    g_esq[row] = s;
}

// ======== GEMM core (R12 config): CTA 128x128, 4 warps (2x2 of 64x64), BK=64,
//          2 stages, 3 CTA/SM, kc-unrolled x2, pointer-bumped loader ========
static constexpr int A_ST   = 128 * 128;             // 16 KB
static constexpr int STAGE  = 2 * A_ST;              // 32 KB
static constexpr int SMEMSZ = 2 * STAGE;             // 64 KB

// MODE 0: E = Xh @ Wh^T (K=1024), store fp16 E + esq partials
// MODE 1: out = 2*(E @ Ch^T) - esq - csq (K=768), store fp32
template<int MODE>
__global__ void __launch_bounds__(128, 3)
gemm_tpl(const __half* __restrict__ A, const __half* __restrict__ B, float* __restrict__ out)
{
    constexpr int K  = (MODE == 0) ? DIN : Dd;
    constexpr int NT = K / 64;                       // 16 / 12 (both even)
    constexpr int LD = K * 2;

    extern __shared__ char smem[];
    const uint32_t sb = smem_u32(smem);
    const int tid = threadIdx.x, wid = tid >> 5, lane = tid & 31;
    const int warp_m = wid >> 1, warp_n = wid & 1;   // 2 x 2
    const int m0 = blockIdx.x * 128, n0 = blockIdx.y * 128;

    const int ldrow = tid >> 3, ldc = (tid & 7) * 16;
    const char* gAr = reinterpret_cast<const char*>(A) + (size_t)(m0 + ldrow) * LD + ldc;
    const char* gBr = reinterpret_cast<const char*>(B) + (size_t)(n0 + ldrow) * LD + ldc;
    const uint32_t sOff0 = swz((uint32_t)(ldrow*128 + ldc));   // row step 16 -> +2048 folds

    // pointer-bumping loader: loads current k-chunk into given stage base, advances 128B
    auto load_stage = [&](uint32_t stage_base){
        const uint32_t base = stage_base + sOff0;
        #pragma unroll
        for (int i = 0; i < 8; i++)
            cp16(base + i*2048, gAr + (size_t)(i*16)*LD);
        #pragma unroll
        for (int i = 0; i < 8; i++)
            cp16(base + A_ST + i*2048, gBr + (size_t)(i*16)*LD);
        cp_commit();
        gAr += 128;
        gBr += 128;
    };

    uint32_t hacc[4][8][2];
    #pragma unroll
    for (int i = 0; i < 4; i++)
        #pragma unroll
        for (int j = 0; j < 8; j++){ hacc[i][j][0] = 0u; hacc[i][j][1] = 0u; }

    load_stage(sb);
    load_stage(sb + STAGE);

    const int lrow = lane & 15, lcol = (lane >> 4) * 16;
    const uint32_t aoff0 = swz((uint32_t)((warp_m*64 + lrow)*128 + lcol));
    const uint32_t boff0 = A_ST + swz((uint32_t)((warp_n*64 + lrow)*128 + lcol));

    auto mma_chunk = [&](uint32_t sbs){
        #pragma unroll
        for (int ks = 0; ks < 4; ks++){
            uint32_t a[4][4], b[4][4];
            const uint32_t kx = (uint32_t)(ks*32);
            const uint32_t axk = sbs + (aoff0 ^ kx);
            const uint32_t bxk = sbs + (boff0 ^ kx);
            #pragma unroll
            for (int i = 0; i < 4; i++) ldsm4(a[i], axk + i*2048);
            #pragma unroll
            for (int j = 0; j < 4; j++) ldsm4(b[j], bxk + j*2048);
            #pragma unroll
            for (int i = 0; i < 4; i++)
                #pragma unroll
                for (int j2 = 0; j2 < 8; j2++)
                    mma_f16(hacc[i][j2], a[i], b[j2>>1][j2&1], b[j2>>1][2 + (j2&1)]);
        }
    };

    #pragma unroll 1
    for (int kc = 0; kc < NT; kc += 2){
        // ---- stage 0 ----
        cp_wait<1>();
        __syncthreads();
        mma_chunk(sb);
        __syncthreads();
        if (kc + 2 < NT) load_stage(sb);
        else             cp_commit();                 // uniform group counting
        // ---- stage 1 ----
        cp_wait<1>();
        __syncthreads();
        mma_chunk(sb + STAGE);
        __syncthreads();
        if (kc + 3 < NT) load_stage(sb + STAGE);
        else             cp_commit();
    }

    // ---------------- epilogue ----------------
    const int quad = lane >> 2, tq = lane & 3;
    if (MODE == 0){
        const int slot = blockIdx.y * 2 + warp_n;    // 6 ntiles x 2 warp_n = 12 slots
        #pragma unroll
        for (int i = 0; i < 4; i++){
            const int mr0 = m0 + warp_m*64 + i*16 + quad;
            float s0 = 0.f, s1 = 0.f;
            #pragma unroll
            for (int j2 = 0; j2 < 8; j2++){
                const int n = n0 + warp_n*64 + j2*8 + tq*2;
                __half2 h0 = *reinterpret_cast<__half2*>(&hacc[i][j2][0]);
                __half2 h1 = *reinterpret_cast<__half2*>(&hacc[i][j2][1]);
                *reinterpret_cast<__half2*>(g_E + (size_t)mr0 * Dd + n)     = h0;
                *reinterpret_cast<__half2*>(g_E + (size_t)(mr0+8) * Dd + n) = h1;
                float2 f0 = __half22float2(h0), f1 = __half22float2(h1);
                s0 += f0.x*f0.x + f0.y*f0.y;
                s1 += f1.x*f1.x + f1.y*f1.y;
            }
            #pragma unroll
            for (int o = 1; o < 4; o <<= 1){
                s0 += __shfl_xor_sync(0xffffffffu, s0, o);
                s1 += __shfl_xor_sync(0xffffffffu, s1, o);
            }
            if (tq == 0){
                g_esqp[(size_t)mr0     * 12 + slot] = s0;
                g_esqp[(size_t)(mr0+8) * 12 + slot] = s1;
            }
        }
    } else {
        #pragma unroll
        for (int i = 0; i < 4; i++){
            const int mr0 = m0 + warp_m*64 + i*16 + quad;
            const float e0 = __ldg(&g_esq[mr0]), e1 = __ldg(&g_esq[mr0 + 8]);
            #pragma unroll
            for (int j2 = 0; j2 < 8; j2++){
                const int n = n0 + warp_n*64 + j2*8 + tq*2;
                const float cs0 = __ldg(&g_csq[n]), cs1 = __ldg(&g_csq[n+1]);
                float2 lo = __half22float2(*reinterpret_cast<__half2*>(&hacc[i][j2][0]));
                float2 hi = __half22float2(*reinterpret_cast<__half2*>(&hacc[i][j2][1]));
                float2 v0 = make_float2(2.f*lo.x - e0 - cs0, 2.f*lo.y - e0 - cs1);
                float2 v1 = make_float2(2.f*hi.x - e1 - cs0, 2.f*hi.y - e1 - cs1);
                *reinterpret_cast<float2*>(out + (size_t)mr0 * Cc + n)     = v0;
                *reinterpret_cast<float2*>(out + (size_t)(mr0+8) * Cc + n) = v1;
            }
        }
    }
}

extern "C" void kernel_launch(void* const* d_in, const int* in_sizes, int n_in,
                              void* d_out, int out_size)
{
    const float* x = (const float*)d_in[0];
    const float* W = (const float*)d_in[1];
    const float* c = (const float*)d_in[2];
    float* out = (float*)d_out;

    cudaFuncSetAttribute(gemm_tpl<0>, cudaFuncAttributeMaxDynamicSharedMemorySize, SMEMSZ);
    cudaFuncSetAttribute(gemm_tpl<1>, cudaFuncAttributeMaxDynamicSharedMemorySize, SMEMSZ);

    prep_x<<<(Bn * DIN / 4) / 256, 256>>>(reinterpret_cast<const float4*>(x));
    prep_w<<<dim3(Dd / 32, DIN / 32), dim3(32, 8)>>>(W);
    prep_cent<<<Cc, 256>>>(c);

    __half *xh, *wh, *eh, *ch;
    cudaGetSymbolAddress((void**)&xh, g_Xh);
    cudaGetSymbolAddress((void**)&wh, g_Wh);
    cudaGetSymbolAddress((void**)&eh, g_E);
    cudaGetSymbolAddress((void**)&ch, g_Ch);

    gemm_tpl<0><<<dim3(Bn / 128, Dd / 128), 128, SMEMSZ>>>(xh, wh, nullptr);
    combine_esq<<<Bn / 256, 256>>>();
    gemm_tpl<1><<<dim3(Bn / 128, Cc / 128), 128, SMEMSZ>>>(eh, ch, out);
}